// round 13
// baseline (speedup 1.0000x reference)
#include <cuda_runtime.h>
#include <math.h>

#define BS 8
#define NP 2048
#define CD 12
#define FD 2
#define DD 24
#define KS 16
#define RPB 4
#define TPB 512
#define MPT 4
#define CAP 64
#define FULLMASK 0xffffffffu

typedef unsigned long long ull;

// smem words: s_ck (RPB*CAP ull) | s_q | s_A | s_T | s_cnt | s_sel
#define SMEM_WORDS (2*RPB*CAP + DD*RPB + RPB*NP + 4*RPB + RPB + RPB*KS)
#define SMEM_BYTES (SMEM_WORDS * 4)

// normalized features, d-major for coalesced m-loads: gFnT[b][d][m]
__device__ float gFnT[BS][DD][NP];

// ---------------------------------------------------------------------------
// prep: normalized features (reference fp32 arithmetic order) + tgt_out copy.
// ---------------------------------------------------------------------------
__global__ void prep_kernel(const float* __restrict__ x, const int* __restrict__ flowp,
                            float* __restrict__ out) {
    int idx = blockIdx.x * blockDim.x + threadIdx.x;
    if (idx >= BS * NP) return;
    int b = idx >> 11;
    int n = idx & (NP - 1);
    int flow = flowp ? flowp[0] : 0;
    const float* xb = x + (size_t)b * (CD * FD * NP);

    float feats[DD];
#pragma unroll
    for (int f = 0; f < FD; f++)
#pragma unroll
        for (int c = 0; c < CD; c++)
            feats[f * CD + c] = xb[(c * FD + f) * NP + n];

    float ss = 0.f;
#pragma unroll
    for (int d = 0; d < DD; d++) ss = __fadd_rn(ss, __fmul_rn(feats[d], feats[d]));
    float denom = __fadd_rn(sqrtf(ss), 1e-8f);
#pragma unroll
    for (int d = 0; d < DD; d++)
        gFnT[b][d][n] = __fdiv_rn(feats[d], denom);

    float* out2 = out + (size_t)BS * NP * KS * CD;
#pragma unroll
    for (int c = 0; c < CD; c++)
        out2[(b * CD + c) * NP + n] = xb[(c * FD + flow) * NP + n];
}

// orderable 64-bit key: (monotone float map) desc, then index asc
__device__ __forceinline__ ull make_key(float v, int idx) {
    unsigned u = __float_as_uint(v);
    u = (u & 0x80000000u) ? ~u : (u | 0x80000000u);
    return ((ull)u << 32) | (unsigned)(NP - 1 - idx);
}
__device__ __forceinline__ int key_idx(ull k) {
    return NP - 1 - (int)(k & 0xffffffffu);
}

// full bitonic sort of 32 keys, descending (lane 0 = largest)
template <typename T_>
__device__ __forceinline__ T_ sort32_desc(T_ v, int lane) {
#pragma unroll
    for (int k2 = 2; k2 <= 32; k2 <<= 1) {
#pragma unroll
        for (int j2 = k2 >> 1; j2 > 0; j2 >>= 1) {
            T_ o = __shfl_xor_sync(FULLMASK, v, j2);
            bool up = ((lane & k2) == 0);
            bool low = ((lane & j2) == 0);
            T_ mx = v > o ? v : o, mn = v > o ? o : v;
            v = (up == low) ? mx : mn;
        }
    }
    return v;
}

// merge: best (desc-sorted) with ch (desc-sorted) -> top-32 of union, desc
__device__ __forceinline__ ull merge32_desc(ull best, ull ch, int lane) {
    ull o = __shfl_sync(FULLMASK, ch, 31 - lane);
    ull v = best > o ? best : o;
#pragma unroll
    for (int j2 = 16; j2 > 0; j2 >>= 1) {
        ull w = __shfl_xor_sync(FULLMASK, v, j2);
        bool low = ((lane & j2) == 0);
        ull mx = v > w ? v : w, mn = v > w ? w : v;
        v = low ? mx : mn;
    }
    return v;
}

// ---------------------------------------------------------------------------
// main: 512 thr, 4 rows/block (low regs -> 3 CTA/SM target).
// Phase 1: scalar register dots -> s_A. Phase 2: warp (r,h) handles quarter
// h of row r: lane-max + bitonic threshold per quarter; T = max of quarters;
// register compaction to u64 keys; rank-based exact top-16; gather.
// ---------------------------------------------------------------------------
__global__ void __launch_bounds__(TPB, 3) main_kernel(const float* __restrict__ x,
                                                      const int* __restrict__ flowp,
                                                      float* __restrict__ out) {
    extern __shared__ float sm[];
    ull*   s_ck  = (ull*)sm;                      // [RPB][CAP] candidate keys
    float* s_q   = (float*)(s_ck + RPB * CAP);    // [DD][RPB]
    float* s_A   = s_q + DD * RPB;                // [RPB][NP]
    float* s_T   = s_A + RPB * NP;                // [RPB][4]
    int*   s_cnt = (int*)(s_T + RPB * 4);         // [RPB]
    int*   s_sel = s_cnt + RPB;                   // [RPB][KS]

    int blk = blockIdx.x;                  // BS * (NP/RPB) = 4096
    int b   = blk >> 9;                    // 512 blocks per batch
    int n0  = (blk & 511) * RPB;
    int tid = threadIdx.x;
    int wid = tid >> 5, lane = tid & 31;

    if (tid < DD * RPB) {
        int d = tid >> 2, r = tid & 3;
        s_q[tid] = gFnT[b][d][n0 + r];
    }
    if (tid < RPB) s_cnt[tid] = 0;
    __syncthreads();

    // ---------------- phase 1: dots (m = 4*tid + j) ----------------
    float acc[RPB][MPT];
#pragma unroll
    for (int r = 0; r < RPB; r++)
#pragma unroll
        for (int j = 0; j < MPT; j++) acc[r][j] = 0.f;

#pragma unroll 6
    for (int d = 0; d < DD; d++) {
        float4 fm = reinterpret_cast<const float4*>(&gFnT[b][d][0])[tid];
        float4 qa = *reinterpret_cast<const float4*>(&s_q[d * RPB]);
        float q[RPB] = {qa.x, qa.y, qa.z, qa.w};
        float f[MPT] = {fm.x, fm.y, fm.z, fm.w};
#pragma unroll
        for (int r = 0; r < RPB; r++)
#pragma unroll
            for (int j = 0; j < MPT; j++)
                acc[r][j] = fmaf(q[r], f[j], acc[r][j]);
    }

#pragma unroll
    for (int r = 0; r < RPB; r++)
        reinterpret_cast<float4*>(s_A + r * NP)[tid] =
            make_float4(acc[r][0], acc[r][1], acc[r][2], acc[r][3]);
    __syncthreads();

    // ---------------- phase 2a: per-quarter lane-max + threshold ------------
    int r = wid & 3, h = wid >> 2;         // h in 0..3, quarter of the row
    const float4* Ar4 = reinterpret_cast<const float4*>(s_A + r * NP);
    int base4 = h * 128 + lane;            // 128 float4 per quarter (512 floats)

    float4 v[4];
#pragma unroll
    for (int j = 0; j < 4; j++) v[j] = Ar4[base4 + 32 * j];

    float lmax = -INFINITY;
#pragma unroll
    for (int j = 0; j < 4; j++)
        lmax = fmaxf(lmax, fmaxf(fmaxf(v[j].x, v[j].y), fmaxf(v[j].z, v[j].w)));

    float sv = sort32_desc(lmax, lane);
    if (lane == 15) s_T[r * 4 + h] = sv;   // 16th-largest lane-max of quarter
    __syncthreads();

    // ---------------- phase 2b: compaction (register-resident values) -------
    {
        float T = fmaxf(fmaxf(s_T[r * 4], s_T[r * 4 + 1]),
                        fmaxf(s_T[r * 4 + 2], s_T[r * 4 + 3]));
        ull* ck = s_ck + r * CAP;
#pragma unroll
        for (int j = 0; j < 4; j++) {
            int mbase = 4 * (base4 + 32 * j);
            float vc[4] = {v[j].x, v[j].y, v[j].z, v[j].w};
#pragma unroll
            for (int c = 0; c < 4; c++) {
                if (vc[c] >= T) {
                    int pos = atomicAdd(&s_cnt[r], 1);
                    if (pos < CAP) ck[pos] = make_key(vc[c], mbase + c);
                }
            }
        }
    }
    __syncthreads();

    // ---------------- phase 2c: rank-based exact top-16 (no shuffles) -------
    {
        int cnt = s_cnt[r];
        ull* ck = s_ck + r * CAP;

        if (cnt <= CAP) {
            // warps h=0,1 rank survivor chunks [h*32, h*32+32)
            if (h < 2) {
                int i = h * 32 + lane;
                if (i < cnt) {
                    ull ki = ck[i];
                    int rank = 0;
                    for (int j = 0; j < cnt; j++)
                        rank += (ck[j] > ki);
                    if (rank < KS) s_sel[r * KS + rank] = key_idx(ki);
                }
            }
        } else if (h == 0) {
            // cold exact fallback: chunk-merge sort over the full row
            const float* Ar = s_A + r * NP;
            ull best = sort32_desc(make_key(Ar[lane], lane), lane);
            for (int c0 = 32; c0 < NP; c0 += 32) {
                int i2 = c0 + lane;
                ull kc = sort32_desc(make_key(Ar[i2], i2), lane);
                best = merge32_desc(best, kc, lane);
            }
            if (lane < KS) s_sel[r * KS + lane] = key_idx(best);
        }
    }
    __syncthreads();

    // ---------------- gather: 4 warps per row, 48 outputs each ----------------
    {
        int n = n0 + r;
        int flow = flowp ? flowp[0] : 0;
        const float* xb = x + (size_t)b * (CD * FD * NP);
        float* o1 = out + (size_t)(b * NP + n) * (KS * CD);
#pragma unroll
        for (int u = 0; u < 2; u++) {
            int t = h * 48 + u * 32 + lane;    // KS*CD = 192 = 4*48
            if (t < h * 48 + 48) {
                int k = t / CD;
                int c = t - k * CD;
                int m = s_sel[r * KS + k];
                o1[t] = xb[(c * FD + flow) * NP + m];
            }
        }
    }
}

extern "C" void kernel_launch(void* const* d_in, const int* in_sizes, int n_in,
                              void* d_out, int out_size) {
    const float* x = (const float*)d_in[0];
    const int* flowp = (n_in >= 2) ? (const int*)d_in[1] : nullptr;
    float* out = (float*)d_out;

    prep_kernel<<<(BS * NP + 255) / 256, 256>>>(x, flowp, out);

    cudaFuncSetAttribute(main_kernel, cudaFuncAttributeMaxDynamicSharedMemorySize, SMEM_BYTES);
    main_kernel<<<BS * (NP / RPB), TPB, SMEM_BYTES>>>(x, flowp, out);
}

// round 14
// speedup vs baseline: 5.2894x; 5.2894x over previous
#include <cuda_runtime.h>
#include <math.h>

#define BS 8
#define NP 2048
#define CD 12
#define FD 2
#define DD 24
#define KS 16
#define RPB 8
#define TPB 512
#define MPT 4
#define CAP 64
#define FULLMASK 0xffffffffu

typedef unsigned long long ull;

// smem words: s_ck (RPB*CAP ull) | s_q | s_A | s_T | s_cnt | s_sel
#define SMEM_WORDS (2*RPB*CAP + DD*RPB + RPB*NP + 2*RPB + RPB + RPB*KS)
#define SMEM_BYTES (SMEM_WORDS * 4)

// normalized features, d-major for coalesced m-loads: gFnT[b][d][m]
__device__ float gFnT[BS][DD][NP];

// ---------------------------------------------------------------------------
// prep: normalized features (reference fp32 arithmetic order) + tgt_out copy.
// ---------------------------------------------------------------------------
__global__ void prep_kernel(const float* __restrict__ x, const int* __restrict__ flowp,
                            float* __restrict__ out) {
    int idx = blockIdx.x * blockDim.x + threadIdx.x;
    if (idx >= BS * NP) return;
    int b = idx >> 11;
    int n = idx & (NP - 1);
    int flow = flowp ? flowp[0] : 0;
    const float* xb = x + (size_t)b * (CD * FD * NP);

    float feats[DD];
#pragma unroll
    for (int f = 0; f < FD; f++)
#pragma unroll
        for (int c = 0; c < CD; c++)
            feats[f * CD + c] = xb[(c * FD + f) * NP + n];

    float ss = 0.f;
#pragma unroll
    for (int d = 0; d < DD; d++) ss = __fadd_rn(ss, __fmul_rn(feats[d], feats[d]));
    float denom = __fadd_rn(sqrtf(ss), 1e-8f);
#pragma unroll
    for (int d = 0; d < DD; d++)
        gFnT[b][d][n] = __fdiv_rn(feats[d], denom);

    float* out2 = out + (size_t)BS * NP * KS * CD;
#pragma unroll
    for (int c = 0; c < CD; c++)
        out2[(b * CD + c) * NP + n] = xb[(c * FD + flow) * NP + n];
}

// orderable 64-bit key: (monotone float map) desc, then index asc
__device__ __forceinline__ ull make_key(float v, int idx) {
    unsigned u = __float_as_uint(v);
    u = (u & 0x80000000u) ? ~u : (u | 0x80000000u);
    return ((ull)u << 32) | (unsigned)(NP - 1 - idx);
}
__device__ __forceinline__ int key_idx(ull k) {
    return NP - 1 - (int)(k & 0xffffffffu);
}

// full bitonic sort of 32 keys, descending (lane 0 = largest)
template <typename T_>
__device__ __forceinline__ T_ sort32_desc(T_ v, int lane) {
#pragma unroll
    for (int k2 = 2; k2 <= 32; k2 <<= 1) {
#pragma unroll
        for (int j2 = k2 >> 1; j2 > 0; j2 >>= 1) {
            T_ o = __shfl_xor_sync(FULLMASK, v, j2);
            bool up = ((lane & k2) == 0);
            bool low = ((lane & j2) == 0);
            T_ mx = v > o ? v : o, mn = v > o ? o : v;
            v = (up == low) ? mx : mn;
        }
    }
    return v;
}

// merge: best (desc-sorted) with ch (desc-sorted) -> top-32 of union, desc
__device__ __forceinline__ ull merge32_desc(ull best, ull ch, int lane) {
    ull o = __shfl_sync(FULLMASK, ch, 31 - lane);
    ull v = best > o ? best : o;
#pragma unroll
    for (int j2 = 16; j2 > 0; j2 >>= 1) {
        ull w = __shfl_xor_sync(FULLMASK, v, j2);
        bool low = ((lane & j2) == 0);
        ull mx = v > w ? v : w, mn = v > w ? w : v;
        v = low ? mx : mn;
    }
    return v;
}

// ---------------------------------------------------------------------------
// main: 512 thr, 8 rows. Phase 1: fully-unrolled scalar register dots -> s_A.
// Phase 2: warp (r,h) = half h of row r: lane-max + bitonic threshold per
// half; T = max of halves; register-resident compaction to u64 keys; rank-
// based exact top-16 (no shuffles); gather on all 16 warps.
// ---------------------------------------------------------------------------
__global__ void __launch_bounds__(TPB, 2) main_kernel(const float* __restrict__ x,
                                                      const int* __restrict__ flowp,
                                                      float* __restrict__ out) {
    extern __shared__ float sm[];
    ull*   s_ck  = (ull*)sm;                      // [RPB][CAP] candidate keys
    float* s_q   = (float*)(s_ck + RPB * CAP);    // [DD][RPB]
    float* s_A   = s_q + DD * RPB;                // [RPB][NP]
    float* s_T   = s_A + RPB * NP;                // [RPB][2]
    int*   s_cnt = (int*)(s_T + RPB * 2);         // [RPB]
    int*   s_sel = s_cnt + RPB;                   // [RPB][KS]

    int blk = blockIdx.x;                  // BS * (NP/RPB) = 2048
    int b   = blk >> 8;
    int n0  = (blk & 255) * RPB;
    int tid = threadIdx.x;
    int wid = tid >> 5, lane = tid & 31;

    const float* __restrict__ gb = &gFnT[b][0][0];   // base: gb[d*NP + m]

    if (tid < DD * RPB) {
        int d = tid >> 3, r = tid & 7;
        s_q[tid] = gb[d * NP + n0 + r];
    }
    if (tid < RPB) s_cnt[tid] = 0;
    __syncthreads();

    // ---------------- phase 1: dots (m = 4*tid + j), full unroll ----------
    float acc[RPB][MPT];
#pragma unroll
    for (int r = 0; r < RPB; r++)
#pragma unroll
        for (int j = 0; j < MPT; j++) acc[r][j] = 0.f;

    {
        const float4* __restrict__ gb4 = reinterpret_cast<const float4*>(gb) + tid;
        const float4* __restrict__ q4  = reinterpret_cast<const float4*>(s_q);
#pragma unroll
        for (int d = 0; d < DD; d++) {
            float4 fm = gb4[d * (NP / 4)];          // immediate offsets off base
            float4 qa = q4[d * 2];
            float4 qb = q4[d * 2 + 1];
            float q[RPB] = {qa.x, qa.y, qa.z, qa.w, qb.x, qb.y, qb.z, qb.w};
            float f[MPT] = {fm.x, fm.y, fm.z, fm.w};
#pragma unroll
            for (int r = 0; r < RPB; r++)
#pragma unroll
                for (int j = 0; j < MPT; j++)
                    acc[r][j] = fmaf(q[r], f[j], acc[r][j]);
        }
    }

#pragma unroll
    for (int r = 0; r < RPB; r++)
        reinterpret_cast<float4*>(s_A + r * NP)[tid] =
            make_float4(acc[r][0], acc[r][1], acc[r][2], acc[r][3]);
    __syncthreads();

    // ---------------- phase 2a: per-half lane-max + threshold ----------------
    int r = wid & 7, h = wid >> 3;
    const float4* Ar4 = reinterpret_cast<const float4*>(s_A + r * NP);
    int base4 = h * 256 + lane;            // float4 index of this lane's first group

    float4 v[8];
#pragma unroll
    for (int j = 0; j < 8; j++) v[j] = Ar4[base4 + 32 * j];

    float lmax = -INFINITY;
#pragma unroll
    for (int j = 0; j < 8; j++)
        lmax = fmaxf(lmax, fmaxf(fmaxf(v[j].x, v[j].y), fmaxf(v[j].z, v[j].w)));

    float sv = sort32_desc(lmax, lane);
    if (lane == 15) s_T[r * 2 + h] = sv;   // 16th-largest lane-max of this half
    __syncthreads();

    // ---------------- phase 2b: compaction (register-resident values) -------
    {
        float T = fmaxf(s_T[r * 2], s_T[r * 2 + 1]);
        ull* ck = s_ck + r * CAP;
#pragma unroll
        for (int j = 0; j < 8; j++) {
            int mbase = 4 * (base4 + 32 * j);
            float vc[4] = {v[j].x, v[j].y, v[j].z, v[j].w};
#pragma unroll
            for (int c = 0; c < 4; c++) {
                if (vc[c] >= T) {
                    int pos = atomicAdd(&s_cnt[r], 1);
                    if (pos < CAP) ck[pos] = make_key(vc[c], mbase + c);
                }
            }
        }
    }
    __syncthreads();

    // ---------------- phase 2c: rank-based exact top-16 (no shuffles) -------
    {
        int cnt = s_cnt[r];
        ull* ck = s_ck + r * CAP;

        if (cnt <= CAP) {
            // warp h ranks survivors [h*32, h*32+32); both warps of row r work
            int i = h * 32 + lane;
            if (i < cnt) {
                ull ki = ck[i];
                int rank = 0;
                for (int j = 0; j < cnt; j++)
                    rank += (ck[j] > ki);
                if (rank < KS) s_sel[r * KS + rank] = key_idx(ki);
            }
        } else if (h == 0) {
            // cold exact fallback: chunk-merge sort over the full row
            const float* Ar = s_A + r * NP;
            ull best = sort32_desc(make_key(Ar[lane], lane), lane);
            for (int c0 = 32; c0 < NP; c0 += 32) {
                int i2 = c0 + lane;
                ull kc = sort32_desc(make_key(Ar[i2], i2), lane);
                best = merge32_desc(best, kc, lane);
            }
            if (lane < KS) s_sel[r * KS + lane] = key_idx(best);
        }
    }
    __syncthreads();

    // ---------------- gather: all 16 warps, half-row each ----------------
    {
        int n = n0 + r;
        int flow = flowp ? flowp[0] : 0;
        const float* xb = x + (size_t)b * (CD * FD * NP);
        float* o1 = out + (size_t)(b * NP + n) * (KS * CD);
#pragma unroll
        for (int u = 0; u < 3; u++) {
            int t = h * 96 + u * 32 + lane;       // KS*CD = 192 = 2*96
            int k = (t * 5462) >> 16;             // t/12 exact for t < 786
            int c = t - k * CD;
            int m = s_sel[r * KS + k];
            o1[t] = xb[(c * FD + flow) * NP + m];
        }
    }
}

extern "C" void kernel_launch(void* const* d_in, const int* in_sizes, int n_in,
                              void* d_out, int out_size) {
    const float* x = (const float*)d_in[0];
    const int* flowp = (n_in >= 2) ? (const int*)d_in[1] : nullptr;
    float* out = (float*)d_out;

    prep_kernel<<<(BS * NP + 255) / 256, 256>>>(x, flowp, out);

    cudaFuncSetAttribute(main_kernel, cudaFuncAttributeMaxDynamicSharedMemorySize, SMEM_BYTES);
    main_kernel<<<BS * (NP / RPB), TPB, SMEM_BYTES>>>(x, flowp, out);
}